// round 15
// baseline (speedup 1.0000x reference)
#include <cuda_runtime.h>
#include <cuda_bf16.h>

#define BATCH 8
#define CCH   256
#define HH    128
#define WW    128
#define QKD   64
#define HW    (HH*WW)
#define MTOT  384

__device__ __forceinline__ unsigned pack_bf16(float lo, float hi) {
    __nv_bfloat162 t = __floats2bfloat162_rn(lo, hi);
    return *reinterpret_cast<unsigned*>(&t);
}

// ---------------- scratch ----------------
// fragment-ordered weights: 24 m16-tiles (0..7 = QK rows 0..127, 8..23 = V rows 128..383)
// layout: [tile][kb(16)][lane(32)] -> uint4 for mma.m16n8k16 A operand
__device__ __align__(16) uint4 g_wfrag[24*16*32];
__device__ float g_bias[MTOT];

// ---------------- prep ----------------
__global__ void prep_w_kernel(const float* __restrict__ wq, const float* __restrict__ bq,
                              const float* __restrict__ wk, const float* __restrict__ bk,
                              const float* __restrict__ wv, const float* __restrict__ bv) {
    int i = blockIdx.x*blockDim.x + threadIdx.x;
    if (i < 24*16*32) {
        int lane = i & 31, kb = (i >> 5) & 15, t = i >> 9;
        int r4 = lane >> 2, c2 = (lane & 3)*2;
        int m = (t < 8) ? t*16 : 128 + (t-8)*16;
        int k = kb*16 + c2;
        int r0 = m + r4, r1 = m + 8 + r4;
        auto fetch = [&](int row, int col) -> float {
            if (row < 64)  return wq[row*CCH + col];
            if (row < 128) return wk[(row-64)*CCH + col];
            return wv[(row-128)*CCH + col];
        };
        uint4 u;
        u.x = pack_bf16(fetch(r0, k),   fetch(r0, k+1));
        u.y = pack_bf16(fetch(r1, k),   fetch(r1, k+1));
        u.z = pack_bf16(fetch(r0, k+8), fetch(r0, k+9));
        u.w = pack_bf16(fetch(r1, k+8), fetch(r1, k+9));
        g_wfrag[i] = u;
    }
    if (i < MTOT) {
        float b;
        if (i < 64)       b = bq[i];
        else if (i < 128) b = bk[i-64];
        else              b = bv[i-128];
        g_bias[i] = b;
    }
}

// ---------------- fused kernel: 512 threads ----------------
#define LDX 136
#define LDQ 136
#define LDO 132
#define OFF_QK  69632                     // sQK 128x136 bf16; later sOa (fp32 64x132)
#define OFF_V   104448                    // sV 128x136 bf16
#define OFF_OB  139264                    // sOb fp32 64x132 = 33792
#define OFF_RED 173056                    // softmax scratch: sMax[128][2], sSum[128][2]
#define FUSED_SMEM 175104

__device__ __forceinline__ void mma16816(float* d, const unsigned* a, unsigned b0, unsigned b1) {
    asm volatile("mma.sync.aligned.m16n8k16.row.col.f32.bf16.bf16.f32 "
        "{%0,%1,%2,%3}, {%4,%5,%6,%7}, {%8,%9}, {%0,%1,%2,%3};\n"
        : "+f"(d[0]), "+f"(d[1]), "+f"(d[2]), "+f"(d[3])
        : "r"(a[0]), "r"(a[1]), "r"(a[2]), "r"(a[3]), "r"(b0), "r"(b1));
}

#define LDSM4T(R0,R1,R2,R3,ADDR) \
    asm volatile("ldmatrix.sync.aligned.m8n8.x4.trans.shared.b16 {%0,%1,%2,%3}, [%4];\n" \
        : "=r"(R0), "=r"(R1), "=r"(R2), "=r"(R3) : "r"(ADDR))
#define LDSM4(R0,R1,R2,R3,ADDR) \
    asm volatile("ldmatrix.sync.aligned.m8n8.x4.shared.b16 {%0,%1,%2,%3}, [%4];\n" \
        : "=r"(R0), "=r"(R1), "=r"(R2), "=r"(R3) : "r"(ADDR))

__global__ void __launch_bounds__(512, 1) fused_kernel(const float* __restrict__ x,
                                                       const float* __restrict__ gamma,
                                                       float* __restrict__ y) {
    extern __shared__ char sm[];
    __nv_bfloat16* xs  = reinterpret_cast<__nv_bfloat16*>(sm);
    __nv_bfloat16* sQK = reinterpret_cast<__nv_bfloat16*>(sm + OFF_QK);
    __nv_bfloat16* sV  = reinterpret_cast<__nv_bfloat16*>(sm + OFF_V);
    float*         sOa = reinterpret_cast<float*>(sm + OFF_QK);
    float*         sOb = reinterpret_cast<float*>(sm + OFF_OB);
    float*         sMax = reinterpret_cast<float*>(sm + OFF_RED);       // [128][2]
    float*         sSum = sMax + 256;                                    // [128][2]

    const int bh = blockIdx.x;
    const int b = bh >> 7, h = bh & 127;
    const int tid = threadIdx.x, wid = tid >> 5, lane = tid & 31;
    const int r4 = lane >> 2;
    const int c2 = (lane & 3) * 2;

    const unsigned ux = (unsigned)__cvta_generic_to_shared(xs);
    const unsigned uq = (unsigned)__cvta_generic_to_shared(sQK);
    const unsigned uk = uq + 64*LDQ*2;
    const unsigned uv = (unsigned)__cvta_generic_to_shared(sV);

    const int kq   = (lane & 7) + ((lane >> 3) & 1) * 8;
    const int nsel = (lane >> 4) & 1;
    const int ka   = (lane & 7) + ((lane >> 4) & 1) * 8;
    const int ma   = ((lane >> 3) & 1) * 8;
    const int no   = (lane >> 4) & 1;
    const int ko   = ((lane >> 3) & 1) * 8;

    const float* xb = x + (size_t)b*CCH*HW + h*WW;

    // ---- load x slice -> bf16 smem xs[channel][pixel] ----
    #pragma unroll
    for (int t = 0; t < 16; t++) {
        int idx = tid + t*512;            // 8192 float4
        int r = idx >> 5, c = idx & 31;
        float4 v = *reinterpret_cast<const float4*>(xb + (size_t)r*HW + c*4);
        __nv_bfloat162 lo = __floats2bfloat162_rn(v.x, v.y);
        __nv_bfloat162 hi = __floats2bfloat162_rn(v.z, v.w);
        uint2 u;
        u.x = *reinterpret_cast<unsigned*>(&lo);
        u.y = *reinterpret_cast<unsigned*>(&hi);
        *reinterpret_cast<uint2*>(xs + r*LDX + c*4) = u;
    }
    __syncthreads();

    // ---- proj Q,K: warp = (tile-pair mp 0..3, pixel-quarter q4 0..3) ----
    {
        const int mp = wid >> 2, q4 = wid & 3;
        const uint4* wf0 = g_wfrag + (mp*2    )*512 + lane;
        const uint4* wf1 = g_wfrag + (mp*2 + 1)*512 + lane;
        float acc[2][4][4];
        #pragma unroll
        for (int tt = 0; tt < 2; tt++)
            #pragma unroll
            for (int nb = 0; nb < 4; nb++) {
                acc[tt][nb][0]=0.f; acc[tt][nb][1]=0.f; acc[tt][nb][2]=0.f; acc[tt][nb][3]=0.f;
            }
        #pragma unroll
        for (int kb = 0; kb < 16; kb++) {
            uint4 aw0 = wf0[kb*32];
            uint4 aw1 = wf1[kb*32];
            unsigned a0[4] = {aw0.x, aw0.y, aw0.z, aw0.w};
            unsigned a1[4] = {aw1.x, aw1.y, aw1.z, aw1.w};
            const unsigned rb = ux + ((kb*16 + kq)*LDX + q4*32)*2;
            #pragma unroll
            for (int njp = 0; njp < 2; njp++) {
                unsigned b0,b1,b2,b3;
                LDSM4T(b0,b1,b2,b3, rb + (njp*2 + nsel)*16);
                mma16816(acc[0][2*njp],   a0, b0, b1);
                mma16816(acc[0][2*njp+1], a0, b2, b3);
                mma16816(acc[1][2*njp],   a1, b0, b1);
                mma16816(acc[1][2*njp+1], a1, b2, b3);
            }
        }
        #pragma unroll
        for (int tt = 0; tt < 2; tt++) {
            const int m0 = (mp*2 + tt)*16;
            const float bias0 = g_bias[m0 + r4], bias1 = g_bias[m0 + r4 + 8];
            #pragma unroll
            for (int nb = 0; nb < 4; nb++) {
                const int col = q4*32 + nb*8 + c2;
                *reinterpret_cast<unsigned*>(sQK + (m0 + r4    )*LDQ + col) =
                    pack_bf16(acc[tt][nb][0] + bias0, acc[tt][nb][1] + bias0);
                *reinterpret_cast<unsigned*>(sQK + (m0 + r4 + 8)*LDQ + col) =
                    pack_bf16(acc[tt][nb][2] + bias1, acc[tt][nb][3] + bias1);
            }
        }
    }
    __syncthreads();

    // ---- S = Q^T K : warp = (16 queries qi, 64-key half kh) ----
    const int qi = wid & 7, kh = wid >> 3;
    const int w0 = qi * 16;
    const int k0px = kh * 64;

    float sacc[8][4];
    #pragma unroll
    for (int nb = 0; nb < 8; nb++) { sacc[nb][0]=0.f; sacc[nb][1]=0.f; sacc[nb][2]=0.f; sacc[nb][3]=0.f; }

    #pragma unroll
    for (int kb = 0; kb < 4; kb++) {
        unsigned a[4];
        LDSM4T(a[0],a[1],a[2],a[3], uq + ((kb*16 + ka)*LDQ + w0 + ma)*2);
        const unsigned rb = uk + ((kb*16 + kq)*LDQ + k0px)*2;
        #pragma unroll
        for (int njp = 0; njp < 4; njp++) {
            unsigned b0,b1,b2,b3;
            LDSM4T(b0,b1,b2,b3, rb + (njp*2 + nsel)*16);
            mma16816(sacc[2*njp],   a, b0, b1);
            mma16816(sacc[2*njp+1], a, b2, b3);
        }
    }

    // ---- split softmax over 128 keys (this warp holds 64) ----
    float mx0 = -1e30f, mx1 = -1e30f;
    #pragma unroll
    for (int nb = 0; nb < 8; nb++) {
        mx0 = fmaxf(mx0, fmaxf(sacc[nb][0], sacc[nb][1]));
        mx1 = fmaxf(mx1, fmaxf(sacc[nb][2], sacc[nb][3]));
    }
    mx0 = fmaxf(mx0, __shfl_xor_sync(0xffffffffu, mx0, 1));
    mx0 = fmaxf(mx0, __shfl_xor_sync(0xffffffffu, mx0, 2));
    mx1 = fmaxf(mx1, __shfl_xor_sync(0xffffffffu, mx1, 1));
    mx1 = fmaxf(mx1, __shfl_xor_sync(0xffffffffu, mx1, 2));
    sMax[(w0 + r4    )*2 + kh] = mx0;
    sMax[(w0 + r4 + 8)*2 + kh] = mx1;
    __syncthreads();
    const float gmx0 = fmaxf(sMax[(w0 + r4    )*2], sMax[(w0 + r4    )*2 + 1]);
    const float gmx1 = fmaxf(sMax[(w0 + r4 + 8)*2], sMax[(w0 + r4 + 8)*2 + 1]);

    float s0 = 0.f, s1 = 0.f;
    #pragma unroll
    for (int nb = 0; nb < 8; nb++) {
        sacc[nb][0] = __expf(sacc[nb][0] - gmx0);
        sacc[nb][1] = __expf(sacc[nb][1] - gmx0);
        sacc[nb][2] = __expf(sacc[nb][2] - gmx1);
        sacc[nb][3] = __expf(sacc[nb][3] - gmx1);
        s0 += sacc[nb][0] + sacc[nb][1];
        s1 += sacc[nb][2] + sacc[nb][3];
    }
    s0 += __shfl_xor_sync(0xffffffffu, s0, 1);
    s0 += __shfl_xor_sync(0xffffffffu, s0, 2);
    s1 += __shfl_xor_sync(0xffffffffu, s1, 1);
    s1 += __shfl_xor_sync(0xffffffffu, s1, 2);
    sSum[(w0 + r4    )*2 + kh] = s0;
    sSum[(w0 + r4 + 8)*2 + kh] = s1;
    __syncthreads();
    const float inv0 = 1.0f / (sSum[(w0 + r4    )*2] + sSum[(w0 + r4    )*2 + 1]);
    const float inv1 = 1.0f / (sSum[(w0 + r4 + 8)*2] + sSum[(w0 + r4 + 8)*2 + 1]);

    // probs -> A fragments for this warp's 64-key slice (k blocks kb 0..3)
    unsigned ap[4][4];
    #pragma unroll
    for (int kb = 0; kb < 4; kb++) {
        ap[kb][0] = pack_bf16(sacc[2*kb  ][0]*inv0, sacc[2*kb  ][1]*inv0);
        ap[kb][1] = pack_bf16(sacc[2*kb  ][2]*inv1, sacc[2*kb  ][3]*inv1);
        ap[kb][2] = pack_bf16(sacc[2*kb+1][0]*inv0, sacc[2*kb+1][1]*inv0);
        ap[kb][3] = pack_bf16(sacc[2*kb+1][2]*inv1, sacc[2*kb+1][3]*inv1);
    }

    const float g = gamma[0];

    // ---- V proj + O, 2 groups of 2 chunks ----
    const int vm = wid & 3, q4v = wid >> 2;   // V proj: warp = (tile vm, pixel-quarter q4v)
    #pragma unroll 1
    for (int gi = 0; gi < 2; gi++) {
        // V proj: both chunks of this group share B fragments
        {
            const uint4* wf0 = g_wfrag + (8 + (gi*2    )*4 + vm)*512 + lane;
            const uint4* wf1 = g_wfrag + (8 + (gi*2 + 1)*4 + vm)*512 + lane;
            float vacc[2][4][4];
            #pragma unroll
            for (int cc = 0; cc < 2; cc++)
                #pragma unroll
                for (int nb = 0; nb < 4; nb++) {
                    vacc[cc][nb][0]=0.f; vacc[cc][nb][1]=0.f;
                    vacc[cc][nb][2]=0.f; vacc[cc][nb][3]=0.f;
                }
            #pragma unroll
            for (int kb = 0; kb < 16; kb++) {
                uint4 aw0 = wf0[kb*32];
                uint4 aw1 = wf1[kb*32];
                unsigned a0[4] = {aw0.x, aw0.y, aw0.z, aw0.w};
                unsigned a1[4] = {aw1.x, aw1.y, aw1.z, aw1.w};
                const unsigned rb = ux + ((kb*16 + kq)*LDX + q4v*32)*2;
                #pragma unroll
                for (int njp = 0; njp < 2; njp++) {
                    unsigned b0,b1,b2,b3;
                    LDSM4T(b0,b1,b2,b3, rb + (njp*2 + nsel)*16);
                    mma16816(vacc[0][2*njp],   a0, b0, b1);
                    mma16816(vacc[0][2*njp+1], a0, b2, b3);
                    mma16816(vacc[1][2*njp],   a1, b0, b1);
                    mma16816(vacc[1][2*njp+1], a1, b2, b3);
                }
            }
            __syncthreads();   // prior O-phase done reading sV
            #pragma unroll
            for (int cc = 0; cc < 2; cc++) {
                const int mg = 128 + (gi*2 + cc)*64 + vm*16;
                const float bias0 = g_bias[mg + r4], bias1 = g_bias[mg + r4 + 8];
                __nv_bfloat16* sVc = sV + cc*64*LDQ;
                #pragma unroll
                for (int nb = 0; nb < 4; nb++) {
                    const int col = q4v*32 + nb*8 + c2;
                    *reinterpret_cast<unsigned*>(sVc + (vm*16 + r4    )*LDQ + col) =
                        pack_bf16(vacc[cc][nb][0] + bias0, vacc[cc][nb][1] + bias0);
                    *reinterpret_cast<unsigned*>(sVc + (vm*16 + r4 + 8)*LDQ + col) =
                        pack_bf16(vacc[cc][nb][2] + bias1, vacc[cc][nb][3] + bias1);
                }
            }
            __syncthreads();
        }

        // O = attn * V^T, 2 chunks; warp = (qi, kh) computes partial over its 64 keys
        #pragma unroll 1
        for (int cc = 0; cc < 2; cc++) {
            const unsigned uvc = uv + cc*64*LDQ*2;
            float oacc[8][4];
            #pragma unroll
            for (int nb = 0; nb < 8; nb++) { oacc[nb][0]=0.f; oacc[nb][1]=0.f; oacc[nb][2]=0.f; oacc[nb][3]=0.f; }
            #pragma unroll
            for (int kb = 0; kb < 4; kb++) {
                #pragma unroll
                for (int nbp = 0; nbp < 4; nbp++) {
                    unsigned b0,b1,b2,b3;
                    LDSM4(b0,b1,b2,b3,
                          uvc + (((nbp*2 + no)*8 + (lane & 7))*LDQ + k0px + kb*16 + ko)*2);
                    mma16816(oacc[2*nbp],   ap[kb], b0, b1);
                    mma16816(oacc[2*nbp+1], ap[kb], b2, b3);
                }
            }

            // stage partial O as fp32 [ch][query] into sOa (kh=0) / sOb (kh=1)
            __syncthreads();   // prior epilogue readers done
            float* sOw = kh ? sOb : sOa;
            #pragma unroll
            for (int nb = 0; nb < 8; nb++) {
                const int chl = nb*8 + c2;
                sOw[ chl   *LDO + w0 + r4    ] = oacc[nb][0];
                sOw[(chl+1)*LDO + w0 + r4    ] = oacc[nb][1];
                sOw[ chl   *LDO + w0 + r4 + 8] = oacc[nb][2];
                sOw[(chl+1)*LDO + w0 + r4 + 8] = oacc[nb][3];
            }
            __syncthreads();

            // epilogue: y = g*(Oa+Ob) + x, coalesced float4
            const int c0 = (gi*2 + cc) * 64;
            #pragma unroll
            for (int t = 0; t < 4; t++) {
                int idx = tid + t*512;            // 2048 float4 = 64 ch x 32
                int r = idx >> 5, cq = idx & 31;
                float4 oa = *reinterpret_cast<const float4*>(sOa + r*LDO + cq*4);
                float4 ob = *reinterpret_cast<const float4*>(sOb + r*LDO + cq*4);
                size_t base = ((size_t)(b*CCH + c0 + r)*HH + h)*WW + cq*4;
                float4 xv = *reinterpret_cast<const float4*>(x + base);
                float4 ov;
                ov.x = g*(oa.x + ob.x) + xv.x;
                ov.y = g*(oa.y + ob.y) + xv.y;
                ov.z = g*(oa.z + ob.z) + xv.z;
                ov.w = g*(oa.w + ob.w) + xv.w;
                *reinterpret_cast<float4*>(y + base) = ov;
            }
        }
    }
}

// ---------------- launch ----------------
extern "C" void kernel_launch(void* const* d_in, const int* in_sizes, int n_in,
                              void* d_out, int out_size) {
    const float* x     = (const float*)d_in[0];
    const float* wq    = (const float*)d_in[1];
    const float* bq    = (const float*)d_in[2];
    const float* wk    = (const float*)d_in[3];
    const float* bk    = (const float*)d_in[4];
    const float* wv    = (const float*)d_in[5];
    const float* bv    = (const float*)d_in[6];
    const float* gamma = (const float*)d_in[7];
    float* y = (float*)d_out;

    prep_w_kernel<<<48, 256>>>(wq, bq, wk, bk, wv, bv);

    cudaFuncSetAttribute(fused_kernel, cudaFuncAttributeMaxDynamicSharedMemorySize, FUSED_SMEM);
    fused_kernel<<<BATCH*HH, 512, FUSED_SMEM>>>(x, gamma, y);
}